// round 2
// baseline (speedup 1.0000x reference)
#include <cuda_runtime.h>
#include <cuda_bf16.h>
#include <math.h>

// Problem constants
#define B_   4
#define S_   2048
#define E_   512
#define H_   8
#define D_   64
#define LOG2_DECAY (-0.07400058144377693f)   // log2(0.95)

typedef unsigned long long u64t;

// Packed f32x2 helpers (sm_103a)
#define FMA2(d, a, b, c) \
    asm("fma.rn.f32x2 %0, %1, %2, %3;" : "=l"(d) : "l"(a), "l"(b), "l"(c))
#define MUL2(d, a, b) \
    asm("mul.rn.f32x2 %0, %1, %2;" : "=l"(d) : "l"(a), "l"(b))

__device__ __forceinline__ u64t pack2(float lo, float hi) {
    u64t r;
    asm("mov.b64 %0, {%1, %2};" : "=l"(r) : "r"(__float_as_uint(lo)), "r"(__float_as_uint(hi)));
    return r;
}
__device__ __forceinline__ void unpack2(u64t v, float& lo, float& hi) {
    unsigned int a, b;
    asm("mov.b64 {%0, %1}, %2;" : "=r"(a), "=r"(b) : "l"(v));
    lo = __uint_as_float(a); hi = __uint_as_float(b);
}

// Scratch (allocation-free: __device__ globals)
__device__ float g_q[B_ * H_ * S_ * D_];     // [B,H,S,D]
__device__ float g_k[B_ * H_ * S_ * D_];
__device__ float g_v[B_ * H_ * S_ * D_];
__device__ float g_attn[B_ * S_ * E_];       // [B,S,E] (= [B,S,H,D])

// ---------------------------------------------------------------------------
// Shared GEMM core: C[m,n] = sum_k A[m,k]*W[n,k] (TN), 128x128 tile, BK=8,
// 256 threads, 8x8 per thread, inner loop packed f32x2.
// Result left in acc2[8][4]; caller does epilogue.
// ---------------------------------------------------------------------------
struct GemmFrag { u64t acc2[8][4]; };

__device__ __forceinline__ void gemm_core(
    const float* __restrict__ A, const float* __restrict__ W,
    int bm, int bn, float (*As)[128], float (*Bs)[128], GemmFrag& fr)
{
    int tid = threadIdx.x;
    int lr = tid >> 1;            // 0..127
    int lc = (tid & 1) * 4;       // 0 or 4
    int tx = tid & 15;
    int ty = tid >> 4;

#pragma unroll
    for (int i = 0; i < 8; i++)
#pragma unroll
        for (int j = 0; j < 4; j++) fr.acc2[i][j] = 0ULL;

    for (int k0 = 0; k0 < 512; k0 += 8) {
        float4 av = *reinterpret_cast<const float4*>(&A[(size_t)(bm + lr) * 512 + k0 + lc]);
        float4 wv = *reinterpret_cast<const float4*>(&W[(size_t)(bn + lr) * 512 + k0 + lc]);
        As[lc + 0][lr] = av.x; As[lc + 1][lr] = av.y;
        As[lc + 2][lr] = av.z; As[lc + 3][lr] = av.w;
        Bs[lc + 0][lr] = wv.x; Bs[lc + 1][lr] = wv.y;
        Bs[lc + 2][lr] = wv.z; Bs[lc + 3][lr] = wv.w;
        __syncthreads();

#pragma unroll
        for (int kk = 0; kk < 8; kk++) {
            float4 a0 = *reinterpret_cast<const float4*>(&As[kk][ty * 8]);
            float4 a1 = *reinterpret_cast<const float4*>(&As[kk][ty * 8 + 4]);
            // b as 4 packed f32x2
            ulonglong2 bl = *reinterpret_cast<const ulonglong2*>(&Bs[kk][tx * 8]);
            ulonglong2 bh = *reinterpret_cast<const ulonglong2*>(&Bs[kk][tx * 8 + 4]);
            u64t b2[4] = {bl.x, bl.y, bh.x, bh.y};
            float a[8] = {a0.x, a0.y, a0.z, a0.w, a1.x, a1.y, a1.z, a1.w};
#pragma unroll
            for (int i = 0; i < 8; i++) {
                u64t ai2 = pack2(a[i], a[i]);
#pragma unroll
                for (int j = 0; j < 4; j++)
                    FMA2(fr.acc2[i][j], ai2, b2[j], fr.acc2[i][j]);
            }
        }
        __syncthreads();
    }
}

// ---------------------------------------------------------------------------
// Fused QKV projection: gridDim.z selects {Q,K,V}; output in [B,H,S,D].
// ---------------------------------------------------------------------------
__global__ __launch_bounds__(256) void qkv_gemm_kernel(
    const float* __restrict__ x,
    const float* __restrict__ Wq, const float* __restrict__ bq,
    const float* __restrict__ Wk, const float* __restrict__ bk,
    const float* __restrict__ Wv, const float* __restrict__ bv)
{
    __shared__ float As[8][128];
    __shared__ float Bs[8][128];

    int mode = blockIdx.z;
    const float* W    = (mode == 0) ? Wq : (mode == 1) ? Wk : Wv;
    const float* bias = (mode == 0) ? bq : (mode == 1) ? bk : bv;
    float* C          = (mode == 0) ? g_q : (mode == 1) ? g_k : g_v;

    int bm = blockIdx.y * 128;
    int bn = blockIdx.x * 128;
    GemmFrag fr;
    gemm_core(x, W, bm, bn, As, Bs, fr);

    int tx = threadIdx.x & 15;
    int ty = threadIdx.x >> 4;
#pragma unroll
    for (int i = 0; i < 8; i++) {
        int m = bm + ty * 8 + i;
        int b = m >> 11, s = m & 2047;
#pragma unroll
        for (int j = 0; j < 4; j++) {
            int n = bn + tx * 8 + j * 2;
            float c0, c1;
            unpack2(fr.acc2[i][j], c0, c1);
            c0 += bias[n];
            c1 += bias[n + 1];
            int h = n >> 6, d = n & 63;   // n, n+1 share the same head (d pairs aligned)
            float* dst = &C[((((size_t)b * H_) + h) * S_ + s) * D_ + d];
            dst[0] = c0; dst[1] = c1;
        }
    }
}

// ---------------------------------------------------------------------------
// Output projection: g_attn[8192,512] @ Wo^T + bo -> out[8192,512]
// ---------------------------------------------------------------------------
__global__ __launch_bounds__(256) void out_gemm_kernel(
    const float* __restrict__ Wo, const float* __restrict__ bo,
    float* __restrict__ out)
{
    __shared__ float As[8][128];
    __shared__ float Bs[8][128];

    int bm = blockIdx.y * 128;
    int bn = blockIdx.x * 128;
    GemmFrag fr;
    gemm_core(g_attn, Wo, bm, bn, As, Bs, fr);

    int tx = threadIdx.x & 15;
    int ty = threadIdx.x >> 4;
#pragma unroll
    for (int i = 0; i < 8; i++) {
        int m = bm + ty * 8 + i;
#pragma unroll
        for (int j = 0; j < 4; j++) {
            int n = bn + tx * 8 + j * 2;
            float c0, c1;
            unpack2(fr.acc2[i][j], c0, c1);
            float2 o = make_float2(c0 + bo[n], c1 + bo[n + 1]);
            *reinterpret_cast<float2*>(&out[(size_t)m * 512 + n]) = o;
        }
    }
}

// ---------------------------------------------------------------------------
// Attention: 1 thread per query row, flash-style online softmax,
// packed f32x2 inner loops. Decay multiplies pre-softmax scores.
// grid = (S/128, B*H), block = 128
// ---------------------------------------------------------------------------
#define KT 16

__global__ __launch_bounds__(128) void attn_kernel()
{
    __shared__ float4 Ks[KT * 16];   // [KT][64] floats
    __shared__ float4 Vs[KT * 16];

    int bh  = blockIdx.y;                       // b*H + h
    int row = blockIdx.x * 128 + threadIdx.x;   // query index in [0,S)

    const float4* qrow = reinterpret_cast<const float4*>(
        g_q + (((size_t)bh * S_) + row) * D_);

    u64t q2[32];                                // 64 d-components as 32 f32x2
#pragma unroll
    for (int i = 0; i < 16; i++) {
        float4 t = qrow[i];
        q2[2 * i]     = pack2(t.x * 0.125f, t.y * 0.125f);   // 1/sqrt(64)
        q2[2 * i + 1] = pack2(t.z * 0.125f, t.w * 0.125f);
    }

    u64t acc2[32];
#pragma unroll
    for (int i = 0; i < 32; i++) acc2[i] = 0ULL;   // {+0.f, +0.f}
    float mmax = -1e30f, l = 0.f;

    const float4* kg4 = reinterpret_cast<const float4*>(g_k + ((size_t)bh * S_) * D_);
    const float4* vg4 = reinterpret_cast<const float4*>(g_v + ((size_t)bh * S_) * D_);

    for (int t0 = 0; t0 < S_; t0 += KT) {
        int f = threadIdx.x;
        int base = (t0 * D_) / 4;
        Ks[f]       = kg4[base + f];
        Ks[f + 128] = kg4[base + f + 128];
        Vs[f]       = vg4[base + f];
        Vs[f + 128] = vg4[base + f + 128];
        __syncthreads();

        // scores: 16 independent packed accumulators
        u64t s2[KT];
#pragma unroll
        for (int j = 0; j < KT; j++) s2[j] = 0ULL;
#pragma unroll
        for (int d4 = 0; d4 < 16; d4++) {
            u64t qa = q2[2 * d4], qb = q2[2 * d4 + 1];
#pragma unroll
            for (int j = 0; j < KT; j++) {
                ulonglong2 kv = *reinterpret_cast<const ulonglong2*>(&Ks[j * 16 + d4]);
                FMA2(s2[j], qa, kv.x, s2[j]);
                FMA2(s2[j], qb, kv.y, s2[j]);
            }
        }

        // horizontal reduce + decay + tile max
        float s[KT];
        float tmax = -1e30f;
#pragma unroll
        for (int j = 0; j < KT; j++) {
            float lo, hi;
            unpack2(s2[j], lo, hi);
            float sv = lo + hi;
            int dt = row - (t0 + j);
            dt = dt < 0 ? -dt : dt;
            sv *= exp2f((float)dt * LOG2_DECAY);
            s[j] = sv;
            tmax = fmaxf(tmax, sv);
        }

        if (tmax > mmax) {
            float mnew = tmax;
            float alpha = __expf(mmax - mnew);
            l *= alpha;
            u64t al2 = pack2(alpha, alpha);
#pragma unroll
            for (int i = 0; i < 32; i++) MUL2(acc2[i], acc2[i], al2);
            mmax = mnew;
        }

        // probs + PV
#pragma unroll
        for (int j = 0; j < KT; j++) {
            float p = __expf(s[j] - mmax);
            l += p;
            u64t p2 = pack2(p, p);
#pragma unroll
            for (int d4 = 0; d4 < 16; d4++) {
                ulonglong2 vv = *reinterpret_cast<const ulonglong2*>(&Vs[j * 16 + d4]);
                FMA2(acc2[2 * d4],     p2, vv.x, acc2[2 * d4]);
                FMA2(acc2[2 * d4 + 1], p2, vv.y, acc2[2 * d4 + 1]);
            }
        }
        __syncthreads();
    }

    float inv = 1.f / l;
    int b = bh >> 3, h = bh & 7;
    float4* o4 = reinterpret_cast<float4*>(
        g_attn + (((size_t)b * S_) + row) * E_ + h * D_);
#pragma unroll
    for (int d4 = 0; d4 < 16; d4++) {
        float x0, x1, x2, x3;
        unpack2(acc2[2 * d4], x0, x1);
        unpack2(acc2[2 * d4 + 1], x2, x3);
        o4[d4] = make_float4(x0 * inv, x1 * inv, x2 * inv, x3 * inv);
    }
}

// ---------------------------------------------------------------------------
extern "C" void kernel_launch(void* const* d_in, const int* in_sizes, int n_in,
                              void* d_out, int out_size)
{
    const float* x  = (const float*)d_in[0];
    const float* Wq = (const float*)d_in[1];
    const float* bq = (const float*)d_in[2];
    const float* Wk = (const float*)d_in[3];
    const float* bk = (const float*)d_in[4];
    const float* Wv = (const float*)d_in[5];
    const float* bv = (const float*)d_in[6];
    const float* Wo = (const float*)d_in[7];
    const float* bo = (const float*)d_in[8];
    float* out = (float*)d_out;

    qkv_gemm_kernel<<<dim3(4, 64, 3), 256>>>(x, Wq, bq, Wk, bk, Wv, bv);
    attn_kernel<<<dim3(S_ / 128, B_ * H_), 128>>>();
    out_gemm_kernel<<<dim3(4, 64), 256>>>(Wo, bo, out);
}